// round 9
// baseline (speedup 1.0000x reference)
#include <cuda_runtime.h>
#include <cstdint>

#define N_NODES 4096
#define D_IN    256
#define D_OUT   128
#define H_HEADS 4
#define NEG_SLOPE 0.2f
#define NWORDS  (N_NODES / 32)

typedef unsigned long long u64;

// ---------------- scratch (device globals; no allocation allowed) ----------------
__device__ float    g_h[H_HEADS * N_NODES * D_OUT];   // 8 MB   h[head][j][o]
__device__ unsigned g_mask[N_NODES * NWORDS];          // 2 MB
__device__ float    g_Ei [H_HEADS * N_NODES];          // exp(s_i)
__device__ float    g_Ei2[H_HEADS * N_NODES];          // exp(0.2*s_i)
__device__ float2   g_jp [H_HEADS * N_NODES];          // (exp(s_j), exp(0.2*s_j))
__device__ float    g_part[2 * H_HEADS * N_NODES * D_OUT];  // 16 MB partial sums
__device__ float    g_Zp  [2 * H_HEADS * N_NODES];          // partial Z

// ---------------- f32x2 helpers (Blackwell packed fp32) ----------------
__device__ __forceinline__ u64 packf2(float lo, float hi) {
    u64 r; asm("mov.b64 %0, {%1, %2};" : "=l"(r) : "f"(lo), "f"(hi)); return r;
}
__device__ __forceinline__ void unpackf2(u64 v, float& lo, float& hi) {
    asm("mov.b64 {%0, %1}, %2;" : "=f"(lo), "=f"(hi) : "l"(v));
}
__device__ __forceinline__ u64 fma2(u64 a, u64 b, u64 c) {
    u64 r; asm("fma.rn.f32x2 %0, %1, %2, %3;" : "=l"(r) : "l"(a), "l"(b), "l"(c)); return r;
}

// ---------------- kernel 1: bit-pack mask = (A>0) | eye ----------------
__global__ void pack_mask_kernel(const int* __restrict__ A) {
    int g    = blockIdx.x * blockDim.x + threadIdx.x;
    int lane = g & 31;
    int word = g >> 5;
    int row  = word >> 7;
    int jw   = word & 127;
    int j    = jw * 32 + lane;
    int v = (A[row * N_NODES + j] > 0) || (j == row);
    unsigned b = __ballot_sync(0xffffffffu, v);
    if (lane == 0) g_mask[word] = b;
}

// ---------------- kernel 2: h = x @ W per head (fp32 tiled GEMM) ----------------
__global__ __launch_bounds__(256) void h_gemm_kernel(const float* __restrict__ x,
                                                     const float* __restrict__ W) {
    __shared__ __align__(16) float xs[32][129];
    __shared__ __align__(16) float ws[32][128];
    int head    = blockIdx.y;
    int rowbase = blockIdx.x * 128;
    int tid = threadIdx.x;
    int tx  = tid & 15;
    int ty  = tid >> 4;
    int o0  = tx * 8;

    float acc[8][8];
#pragma unroll
    for (int u = 0; u < 8; u++)
#pragma unroll
        for (int i = 0; i < 8; i++) acc[u][i] = 0.f;

    const float* Wh = W + head * D_IN * D_OUT;

    for (int k0 = 0; k0 < D_IN; k0 += 32) {
        __syncthreads();
#pragma unroll
        for (int u = 0; u < 4; u++) {
            int e4  = tid + u * 256;
            int row = e4 >> 3, kq = e4 & 7;
            float4 v = *(const float4*)&x[(rowbase + row) * D_IN + k0 + kq * 4];
            xs[kq * 4 + 0][row] = v.x;
            xs[kq * 4 + 1][row] = v.y;
            xs[kq * 4 + 2][row] = v.z;
            xs[kq * 4 + 3][row] = v.w;
        }
#pragma unroll
        for (int u = 0; u < 4; u++) {
            int e4 = tid + u * 256;
            int kk = e4 >> 5, oq = e4 & 31;
            *(float4*)&ws[kk][oq * 4] = *(const float4*)&Wh[(k0 + kk) * D_OUT + oq * 4];
        }
        __syncthreads();
#pragma unroll
        for (int kk = 0; kk < 32; kk++) {
            float wv[8];
            *(float4*)&wv[0] = *(const float4*)&ws[kk][o0];
            *(float4*)&wv[4] = *(const float4*)&ws[kk][o0 + 4];
#pragma unroll
            for (int u = 0; u < 8; u++) {
                float xv = xs[kk][ty + u * 16];
#pragma unroll
                for (int i = 0; i < 8; i++) acc[u][i] += xv * wv[i];
            }
        }
    }
#pragma unroll
    for (int u = 0; u < 8; u++) {
        int row = rowbase + ty + u * 16;
        float* dst = &g_h[(head * N_NODES + row) * D_OUT + o0];
        *(float4*)&dst[0] = make_float4(acc[u][0], acc[u][1], acc[u][2], acc[u][3]);
        *(float4*)&dst[4] = make_float4(acc[u][4], acc[u][5], acc[u][6], acc[u][7]);
    }
}

// ---------------- kernel 3: s_i, s_j and separable exp factors ----------------
__global__ void sij_kernel(const float* __restrict__ a) {
    int head = blockIdx.y;
    int warp = threadIdx.x >> 5, lane = threadIdx.x & 31;
    int row  = blockIdx.x * 8 + warp;
    const float* hrow = &g_h[(head * N_NODES + row) * D_OUT];
    const float* ah   = a + head * 2 * D_OUT;
    float s1 = 0.f, s2 = 0.f;
#pragma unroll
    for (int u = 0; u < 4; u++) {
        int o = lane + u * 32;
        float hv = hrow[o];
        s1 += hv * ah[o];
        s2 += hv * ah[D_OUT + o];
    }
#pragma unroll
    for (int off = 16; off; off >>= 1) {
        s1 += __shfl_xor_sync(0xffffffffu, s1, off);
        s2 += __shfl_xor_sync(0xffffffffu, s2, off);
    }
    if (lane == 0) {
        g_Ei [head * N_NODES + row] = expf(s1);
        g_Ei2[head * N_NODES + row] = expf(NEG_SLOPE * s1);
        g_jp [head * N_NODES + row] = make_float2(expf(s2), expf(NEG_SLOPE * s2));
    }
}

// ---------------- kernel 4: masked-softmax aggregation (v5) ----------------
// Grid (64, 4, 2): 64 rows x one head x one j-half; 128 threads.
// Per tile: threads 0..63 compute the 64x32 weight matrix ONCE (pre-packed
// {w,w} u64 in wsm), accumulating per-row Z in a register (each row owned by
// exactly one thread). fma loop per jj: 2 LDS.128 (packed weights for 4 rows,
// broadcast over tx) + 4 staggered LDS.128 (h) + 32 fma2 -> ~80% fma density.
__global__ __launch_bounds__(128) void agg_kernel() {
    __shared__ __align__(16) float hsm[32 * 128];    // 16 KB: 32 j x 128 o
    __shared__ __align__(16) u64   wsm[32 * 64];     // 16 KB: packed {w,w}[jj][row]

    int head    = blockIdx.y;
    int half    = blockIdx.z;
    int rowbase = blockIdx.x * 64;
    int tid = threadIdx.x;
    int tx  = tid & 7;
    int ty  = tid >> 3;
    int o0  = tx * 16;
    int sh  = tx >> 1;
    int r0  = rowbase + ty * 4;

    // weight-pass state: thread tid<64 owns row rowbase+tid
    float eiw = 0.f, ei2w = 0.f, Zrow = 0.f;
    if (tid < 64) {
        eiw  = g_Ei [head * N_NODES + rowbase + tid];
        ei2w = g_Ei2[head * N_NODES + rowbase + tid];
    }

    u64 acc[4][8];
#pragma unroll
    for (int u = 0; u < 4; u++)
#pragma unroll
        for (int k = 0; k < 8; k++) acc[u][k] = 0ull;

    const float4* hsrc = (const float4*)&g_h[head * N_NODES * D_OUT];
    const float2* jpb  = &g_jp[head * N_NODES];

    int jbeg = half * (N_NODES / 2);
    int jend = jbeg + (N_NODES / 2);

    for (int jt = jbeg; jt < jend; jt += 32) {
        __syncthreads();
        {   // stage 32x128 h tile (all threads, coalesced)
            const float4* src = hsrc + jt * (D_OUT / 4);
            float4* dst = (float4*)hsm;
#pragma unroll
            for (int u = 0; u < 8; u++) dst[tid + u * 128] = src[tid + u * 128];
        }
        if (tid < 64) {   // weight pass: one row per thread, 32 jj
            unsigned mrow = g_mask[(rowbase + tid) * NWORDS + (jt >> 5)];
#pragma unroll 8
            for (int jj = 0; jj < 32; jj++) {
                float2 p = jpb[jt + jj];          // warp-uniform -> broadcast LDG
                float v = fmaxf(eiw * p.x, ei2w * p.y);
                float w = ((mrow >> jj) & 1u) ? v : 0.f;
                Zrow += w;
                wsm[jj * 64 + tid] = packf2(w, w);
            }
        }
        __syncthreads();

#pragma unroll 4
        for (int jj = 0; jj < 32; jj++) {
            // packed weights for this thread's 4 rows (broadcast across tx)
            ulonglong2 wp0 = *(const ulonglong2*)&wsm[jj * 64 + ty * 4];
            ulonglong2 wp1 = *(const ulonglong2*)&wsm[jj * 64 + ty * 4 + 2];
            const float* hrow = hsm + jj * 128 + o0;
#pragma unroll
            for (int k = 0; k < 4; k++) {
                ulonglong2 hv = *(const ulonglong2*)(hrow + (((k + sh) & 3) << 2));
                acc[0][2 * k    ] = fma2(wp0.x, hv.x, acc[0][2 * k    ]);
                acc[0][2 * k + 1] = fma2(wp0.x, hv.y, acc[0][2 * k + 1]);
                acc[1][2 * k    ] = fma2(wp0.y, hv.x, acc[1][2 * k    ]);
                acc[1][2 * k + 1] = fma2(wp0.y, hv.y, acc[1][2 * k + 1]);
                acc[2][2 * k    ] = fma2(wp1.x, hv.x, acc[2][2 * k    ]);
                acc[2][2 * k + 1] = fma2(wp1.x, hv.y, acc[2][2 * k + 1]);
                acc[3][2 * k    ] = fma2(wp1.y, hv.x, acc[3][2 * k    ]);
                acc[3][2 * k + 1] = fma2(wp1.y, hv.y, acc[3][2 * k + 1]);
            }
        }
    }

    int base = (half * H_HEADS + head) * N_NODES;
    if (tid < 64) g_Zp[base + rowbase + tid] = Zrow;
#pragma unroll
    for (int u = 0; u < 4; u++) {
        float* dst = &g_part[(u64)(base + r0 + u) * D_OUT + o0];
#pragma unroll
        for (int k = 0; k < 4; k++) {
            int c4 = ((k + sh) & 3) << 2;     // de-rotate on store
            float f0, f1, f2, f3;
            unpackf2(acc[u][2 * k],     f0, f1);
            unpackf2(acc[u][2 * k + 1], f2, f3);
            *(float4*)&dst[c4] = make_float4(f0, f1, f2, f3);
        }
    }
}

// ---------------- kernel 5: combine halves + softmax normalize ----------------
__global__ void normalize_kernel(float* __restrict__ out) {
    int t    = blockIdx.x * blockDim.x + threadIdx.x;     // 524288 float4s
    int o4   = t & 31;
    int head = (t >> 5) & 3;
    int row  = t >> 7;

    int b0 = head * N_NODES + row;
    int b1 = (H_HEADS + head) * N_NODES + row;
    float Zt = g_Zp[b0] + g_Zp[b1];
    float inv = 1.f / Zt;

    float4 p0 = *(const float4*)&g_part[(u64)b0 * D_OUT + o4 * 4];
    float4 p1 = *(const float4*)&g_part[(u64)b1 * D_OUT + o4 * 4];
    float4 r = make_float4((p0.x + p1.x) * inv, (p0.y + p1.y) * inv,
                           (p0.z + p1.z) * inv, (p0.w + p1.w) * inv);
    *(float4*)&out[(u64)row * 512 + head * D_OUT + o4 * 4] = r;
}

// ---------------- launch ----------------
extern "C" void kernel_launch(void* const* d_in, const int* in_sizes, int n_in,
                              void* d_out, int out_size) {
    const float* x = (const float*)d_in[0];
    const int*   A = (const int*)  d_in[1];
    const float* W = (const float*)d_in[2];
    const float* a = (const float*)d_in[3];
    float* out = (float*)d_out;

    pack_mask_kernel<<<(N_NODES * N_NODES) / 256, 256>>>(A);
    h_gemm_kernel<<<dim3(N_NODES / 128, H_HEADS), 256>>>(x, W);
    sij_kernel<<<dim3(N_NODES / 8, H_HEADS), 256>>>(a);
    agg_kernel<<<dim3(N_NODES / 64, H_HEADS, 2), 128>>>();
    normalize_kernel<<<(N_NODES * H_HEADS * (D_OUT / 4)) / 256, 256>>>(out);
}

// round 12
// speedup vs baseline: 1.9954x; 1.9954x over previous
#include <cuda_runtime.h>
#include <cuda_bf16.h>
#include <cstdint>

#define N_NODES 4096
#define D_IN    256
#define D_OUT   128
#define H_HEADS 4
#define NEG_SLOPE 0.2f
#define NWORDS  (N_NODES / 32)

typedef unsigned long long u64;

// ---------------- scratch (device globals; no allocation allowed) ----------------
__device__ float          g_h[H_HEADS * N_NODES * D_OUT];     // 8 MB fp32 h[head][j][o]
__device__ unsigned       g_mask[N_NODES * NWORDS];            // 2 MB
__device__ float          g_Ei [H_HEADS * N_NODES];
__device__ float          g_Ei2[H_HEADS * N_NODES];
__device__ float2         g_jp [H_HEADS * N_NODES];            // (exp(s_j), exp(0.2*s_j))
__device__ __nv_bfloat16  g_hbhi[H_HEADS * N_NODES * D_OUT];   // 4 MB  h hi [head][j][o]
__device__ __nv_bfloat16  g_hblo[H_HEADS * N_NODES * D_OUT];   // 4 MB  h lo

// ---------------- kernel 1: bit-pack mask = (A>0) | eye ----------------
__global__ void pack_mask_kernel(const int* __restrict__ A) {
    int g    = blockIdx.x * blockDim.x + threadIdx.x;
    int lane = g & 31;
    int word = g >> 5;
    int row  = word >> 7;
    int jw   = word & 127;
    int j    = jw * 32 + lane;
    int v = (A[row * N_NODES + j] > 0) || (j == row);
    unsigned b = __ballot_sync(0xffffffffu, v);
    if (lane == 0) g_mask[word] = b;
}

// ---------------- kernel 2: h = x @ W per head (fp32 tiled GEMM) ----------------
__global__ __launch_bounds__(256) void h_gemm_kernel(const float* __restrict__ x,
                                                     const float* __restrict__ W) {
    __shared__ __align__(16) float xs[32][129];
    __shared__ __align__(16) float ws[32][128];
    int head    = blockIdx.y;
    int rowbase = blockIdx.x * 128;
    int tid = threadIdx.x;
    int tx  = tid & 15;
    int ty  = tid >> 4;
    int o0  = tx * 8;

    float acc[8][8];
#pragma unroll
    for (int u = 0; u < 8; u++)
#pragma unroll
        for (int i = 0; i < 8; i++) acc[u][i] = 0.f;

    const float* Wh = W + head * D_IN * D_OUT;

    for (int k0 = 0; k0 < D_IN; k0 += 32) {
        __syncthreads();
#pragma unroll
        for (int u = 0; u < 4; u++) {
            int e4  = tid + u * 256;
            int row = e4 >> 3, kq = e4 & 7;
            float4 v = *(const float4*)&x[(rowbase + row) * D_IN + k0 + kq * 4];
            xs[kq * 4 + 0][row] = v.x;
            xs[kq * 4 + 1][row] = v.y;
            xs[kq * 4 + 2][row] = v.z;
            xs[kq * 4 + 3][row] = v.w;
        }
#pragma unroll
        for (int u = 0; u < 4; u++) {
            int e4 = tid + u * 256;
            int kk = e4 >> 5, oq = e4 & 31;
            *(float4*)&ws[kk][oq * 4] = *(const float4*)&Wh[(k0 + kk) * D_OUT + oq * 4];
        }
        __syncthreads();
#pragma unroll
        for (int kk = 0; kk < 32; kk++) {
            float wv[8];
            *(float4*)&wv[0] = *(const float4*)&ws[kk][o0];
            *(float4*)&wv[4] = *(const float4*)&ws[kk][o0 + 4];
#pragma unroll
            for (int u = 0; u < 8; u++) {
                float xv = xs[kk][ty + u * 16];
#pragma unroll
                for (int i = 0; i < 8; i++) acc[u][i] += xv * wv[i];
            }
        }
    }
#pragma unroll
    for (int u = 0; u < 8; u++) {
        int row = rowbase + ty + u * 16;
        float* dst = &g_h[(head * N_NODES + row) * D_OUT + o0];
        *(float4*)&dst[0] = make_float4(acc[u][0], acc[u][1], acc[u][2], acc[u][3]);
        *(float4*)&dst[4] = make_float4(acc[u][4], acc[u][5], acc[u][6], acc[u][7]);
    }
}

// ---------------- kernel 3: s_i, s_j and separable exp factors ----------------
__global__ void sij_kernel(const float* __restrict__ a) {
    int head = blockIdx.y;
    int warp = threadIdx.x >> 5, lane = threadIdx.x & 31;
    int row  = blockIdx.x * 8 + warp;
    const float* hrow = &g_h[(head * N_NODES + row) * D_OUT];
    const float* ah   = a + head * 2 * D_OUT;
    float s1 = 0.f, s2 = 0.f;
#pragma unroll
    for (int u = 0; u < 4; u++) {
        int o = lane + u * 32;
        float hv = hrow[o];
        s1 += hv * ah[o];
        s2 += hv * ah[D_OUT + o];
    }
#pragma unroll
    for (int off = 16; off; off >>= 1) {
        s1 += __shfl_xor_sync(0xffffffffu, s1, off);
        s2 += __shfl_xor_sync(0xffffffffu, s2, off);
    }
    if (lane == 0) {
        g_Ei [head * N_NODES + row] = expf(s1);
        g_Ei2[head * N_NODES + row] = expf(NEG_SLOPE * s1);
        g_jp [head * N_NODES + row] = make_float2(expf(s2), expf(NEG_SLOPE * s2));
    }
}

// ---------------- kernel 3b: hi/lo bf16 split of h (same [j][o] layout) --------
__global__ __launch_bounds__(256) void hsplit_kernel() {
    int t = blockIdx.x * blockDim.x + threadIdx.x;      // 524288 threads x 4 elems
    float4 v = *((const float4*)g_h + t);
    __nv_bfloat16 h0 = __float2bfloat16(v.x), h1 = __float2bfloat16(v.y);
    __nv_bfloat16 h2 = __float2bfloat16(v.z), h3 = __float2bfloat16(v.w);
    __nv_bfloat16 l0 = __float2bfloat16(v.x - __bfloat162float(h0));
    __nv_bfloat16 l1 = __float2bfloat16(v.y - __bfloat162float(h1));
    __nv_bfloat16 l2 = __float2bfloat16(v.z - __bfloat162float(h2));
    __nv_bfloat16 l3 = __float2bfloat16(v.w - __bfloat162float(h3));
    unsigned hiA = (unsigned)__bfloat16_as_ushort(h0) | ((unsigned)__bfloat16_as_ushort(h1) << 16);
    unsigned hiB = (unsigned)__bfloat16_as_ushort(h2) | ((unsigned)__bfloat16_as_ushort(h3) << 16);
    unsigned loA = (unsigned)__bfloat16_as_ushort(l0) | ((unsigned)__bfloat16_as_ushort(l1) << 16);
    unsigned loB = (unsigned)__bfloat16_as_ushort(l2) | ((unsigned)__bfloat16_as_ushort(l3) << 16);
    ((uint2*)g_hbhi)[t] = make_uint2(hiA, hiB);
    ((uint2*)g_hblo)[t] = make_uint2(loA, loB);
}

// ================= mma.sync helpers (sm_80 baseline PTX — compiles for sm_100) ==
#define LDSM_X4(r0, r1, r2, r3, addr) \
    asm volatile("ldmatrix.sync.aligned.m8n8.x4.shared.b16 {%0,%1,%2,%3}, [%4];" \
                 : "=r"(r0), "=r"(r1), "=r"(r2), "=r"(r3) : "r"(addr))
#define LDSM_X4T(r0, r1, r2, r3, addr) \
    asm volatile("ldmatrix.sync.aligned.m8n8.x4.trans.shared.b16 {%0,%1,%2,%3}, [%4];" \
                 : "=r"(r0), "=r"(r1), "=r"(r2), "=r"(r3) : "r"(addr))
#define MMA_BF16(d, a0, a1, a2, a3, b0, b1) \
    asm volatile("mma.sync.aligned.m16n8k16.row.col.f32.bf16.bf16.f32 " \
                 "{%0,%1,%2,%3}, {%4,%5,%6,%7}, {%8,%9}, {%0,%1,%2,%3};" \
                 : "+f"((d)[0]), "+f"((d)[1]), "+f"((d)[2]), "+f"((d)[3]) \
                 : "r"(a0), "r"(a1), "r"(a2), "r"(a3), "r"(b0), "r"(b1))

__device__ __forceinline__ uint32_t smem_u32(const void* p) {
    uint32_t a;
    asm("{ .reg .u64 t; cvta.to.shared.u64 t, %1; cvt.u32.u64 %0, t; }" : "=r"(a) : "l"(p));
    return a;
}

// dynamic smem layout (bytes)
#define SM_WHI  0          // W hi  [128 i][64 j] bf16, 128B rows, swz kc^(i&7)
#define SM_WLO  16384
#define SM_HHI  32768      // H hi  [64 j][128 o] bf16, 256B rows, swz oc^(j&7)
#define SM_HLO  49152
#define SM_Z    65536      // 256 floats
#define AGG_SMEM 66560

// ---------------- kernel 4: tensor-core (mma.sync) masked-softmax aggregation ---
// Grid (32, 4), 256 threads (8 warps). Block: 128 rows x 128 o x one head.
// j-tiles of 64. Per tile: gen W hi/lo bf16 (+ fp32 Z), stage H hi/lo,
// each warp computes a 32(i) x 64(o) D-tile via m16n8k16 bf16 MMAs with
// 3-way hi/lo split (Whi*Hhi + Whi*Hlo + Wlo*Hhi). Epilogue: *1/Z, STG.
__global__ __launch_bounds__(256) void agg_kernel(float* __restrict__ out) {
    extern __shared__ __align__(1024) char dsm[];
    uint32_t sb = smem_u32(dsm);
    int tid  = threadIdx.x;
    int lane = tid & 31;
    int wid  = tid >> 5;
    int head = blockIdx.y;
    int rowbase = blockIdx.x * 128;

    // warp tile: rows wy*32, cols wx*64
    int wy = wid >> 1, wx = wid & 1;

    // weight-gen mapping: 2 threads per row (seg = j-half of 64-tile)
    int grow = tid & 127, seg = tid >> 7;
    float eiw  = g_Ei [head * N_NODES + rowbase + grow];
    float ei2w = g_Ei2[head * N_NODES + rowbase + grow];
    float Zrow = 0.f;
    const float2* jpb = &g_jp[head * N_NODES];
    const unsigned* maskrow = &g_mask[(size_t)(rowbase + grow) * NWORDS];
    int wgenbase = grow * 128;      // W row byte base
    int wrx = grow & 7;

    const uint4* hhiG = (const uint4*)(g_hbhi + (size_t)head * N_NODES * D_OUT);
    const uint4* hloG = (const uint4*)(g_hblo + (size_t)head * N_NODES * D_OUT);

    float acc[2][8][4];
#pragma unroll
    for (int m = 0; m < 2; m++)
#pragma unroll
        for (int n = 0; n < 8; n++)
#pragma unroll
            for (int e = 0; e < 4; e++) acc[m][n][e] = 0.f;

    // ldmatrix lane addressing pieces
    int lt = lane >> 3, lr = lane & 7;      // tile index 0..3, row-in-tile 0..7

    for (int t = 0; t < 64; t++) {
        int jt = t * 64;
        __syncthreads();
        // ---- W gen: 32 j per thread, hi/lo bf16, swizzled STS.128 ----
        {
            unsigned mword = maskrow[(jt >> 5) + seg];
#pragma unroll
            for (int cc = 0; cc < 4; cc++) {
                int kc = seg * 4 + cc;
                unsigned hiP[4], loP[4];
#pragma unroll
                for (int e2 = 0; e2 < 4; e2++) {
                    int bit = cc * 8 + e2 * 2;
                    int jg  = jt + seg * 32 + cc * 8 + e2 * 2;
                    float2 pa = jpb[jg];
                    float2 pb = jpb[jg + 1];
                    float va = fmaxf(eiw * pa.x, ei2w * pa.y);
                    float vb = fmaxf(eiw * pb.x, ei2w * pb.y);
                    float wa = ((mword >> bit) & 1u) ? va : 0.f;
                    float wb = ((mword >> (bit + 1)) & 1u) ? vb : 0.f;
                    Zrow += wa + wb;
                    __nv_bfloat16 ha = __float2bfloat16(wa);
                    __nv_bfloat16 hb = __float2bfloat16(wb);
                    __nv_bfloat16 la = __float2bfloat16(wa - __bfloat162float(ha));
                    __nv_bfloat16 lb = __float2bfloat16(wb - __bfloat162float(hb));
                    hiP[e2] = (unsigned)__bfloat16_as_ushort(ha) | ((unsigned)__bfloat16_as_ushort(hb) << 16);
                    loP[e2] = (unsigned)__bfloat16_as_ushort(la) | ((unsigned)__bfloat16_as_ushort(lb) << 16);
                }
                int sw = wgenbase + ((kc ^ wrx) << 4);
                *(uint4*)(dsm + SM_WHI + sw) = make_uint4(hiP[0], hiP[1], hiP[2], hiP[3]);
                *(uint4*)(dsm + SM_WLO + sw) = make_uint4(loP[0], loP[1], loP[2], loP[3]);
            }
        }
        // ---- H stage: 64 j x 128 o hi+lo, coalesced LDG.128 + swizzled STS ----
        {
#pragma unroll
            for (int r = 0; r < 4; r++) {
                int id = tid + r * 256;            // 0..1023 chunk id
                int j  = id >> 4, oc = id & 15;
                size_t gidx = (size_t)(jt + j) * 16 + oc;   // uint4 index in [j][o]
                int ad = j * 256 + ((oc ^ (j & 7)) << 4);
                *(uint4*)(dsm + SM_HHI + ad) = hhiG[gidx];
                *(uint4*)(dsm + SM_HLO + ad) = hloG[gidx];
            }
        }
        __syncthreads();
        // ---- MMA: per warp, 4 ksteps of 16 j ----
#pragma unroll
        for (int ks = 0; ks < 4; ks++) {
            // A frags (2 m-tiles, hi+lo): lane addr per canonical x4 mapping
            uint32_t ahi[2][4], alo[2][4];
#pragma unroll
            for (int mm = 0; mm < 2; mm++) {
                int row = wy * 32 + mm * 16 + (lt & 1) * 8 + lr;
                int kc  = ks * 2 + (lt >> 1);
                uint32_t aaddr = sb + SM_WHI + row * 128 + ((kc ^ (row & 7)) << 4);
                LDSM_X4(ahi[mm][0], ahi[mm][1], ahi[mm][2], ahi[mm][3], aaddr);
                LDSM_X4(alo[mm][0], alo[mm][1], alo[mm][2], alo[mm][3], aaddr + 16384);
            }
#pragma unroll
            for (int nn = 0; nn < 4; nn++) {       // n16 groups
                int j  = ks * 16 + (lt & 1) * 8 + lr;
                int oc = wx * 8 + nn * 2 + (lt >> 1);
                uint32_t baddr = sb + SM_HHI + j * 256 + ((oc ^ (j & 7)) << 4);
                uint32_t bh0, bh1, bh2, bh3, bl0, bl1, bl2, bl3;
                LDSM_X4T(bh0, bh1, bh2, bh3, baddr);
                LDSM_X4T(bl0, bl1, bl2, bl3, baddr + 16384);
#pragma unroll
                for (int mm = 0; mm < 2; mm++) {
                    MMA_BF16(acc[mm][nn * 2],     ahi[mm][0], ahi[mm][1], ahi[mm][2], ahi[mm][3], bh0, bh1);
                    MMA_BF16(acc[mm][nn * 2 + 1], ahi[mm][0], ahi[mm][1], ahi[mm][2], ahi[mm][3], bh2, bh3);
                    MMA_BF16(acc[mm][nn * 2],     ahi[mm][0], ahi[mm][1], ahi[mm][2], ahi[mm][3], bl0, bl1);
                    MMA_BF16(acc[mm][nn * 2 + 1], ahi[mm][0], ahi[mm][1], ahi[mm][2], ahi[mm][3], bl2, bl3);
                    MMA_BF16(acc[mm][nn * 2],     alo[mm][0], alo[mm][1], alo[mm][2], alo[mm][3], bh0, bh1);
                    MMA_BF16(acc[mm][nn * 2 + 1], alo[mm][0], alo[mm][1], alo[mm][2], alo[mm][3], bh2, bh3);
                }
            }
        }
    }

    // ---- Z + epilogue ----
    ((float*)(dsm + SM_Z))[tid] = Zrow;     // zs[seg*128 + grow]
    __syncthreads();
    const float* zs = (const float*)(dsm + SM_Z);

#pragma unroll
    for (int mm = 0; mm < 2; mm++) {
        int r0 = wy * 32 + mm * 16 + (lane >> 2);
        int r1 = r0 + 8;
        float iz0 = 1.f / (zs[r0] + zs[128 + r0]);
        float iz1 = 1.f / (zs[r1] + zs[128 + r1]);
        float* d0 = out + (size_t)(rowbase + r0) * (H_HEADS * D_OUT) + head * D_OUT;
        float* d1 = out + (size_t)(rowbase + r1) * (H_HEADS * D_OUT) + head * D_OUT;
#pragma unroll
        for (int nn = 0; nn < 8; nn++) {
            int col = wx * 64 + nn * 8 + (lane & 3) * 2;
            *(float2*)(d0 + col) = make_float2(acc[mm][nn][0] * iz0, acc[mm][nn][1] * iz0);
            *(float2*)(d1 + col) = make_float2(acc[mm][nn][2] * iz1, acc[mm][nn][3] * iz1);
        }
    }
}

// ---------------- launch ----------------
extern "C" void kernel_launch(void* const* d_in, const int* in_sizes, int n_in,
                              void* d_out, int out_size) {
    const float* x = (const float*)d_in[0];
    const int*   A = (const int*)  d_in[1];
    const float* W = (const float*)d_in[2];
    const float* a = (const float*)d_in[3];
    float* out = (float*)d_out;

    cudaFuncSetAttribute(agg_kernel, cudaFuncAttributeMaxDynamicSharedMemorySize, AGG_SMEM);

    pack_mask_kernel<<<(N_NODES * N_NODES) / 256, 256>>>(A);
    h_gemm_kernel<<<dim3(N_NODES / 128, H_HEADS), 256>>>(x, W);
    sij_kernel<<<dim3(N_NODES / 8, H_HEADS), 256>>>(a);
    hsplit_kernel<<<(H_HEADS * N_NODES * D_OUT) / 1024, 256>>>();
    agg_kernel<<<dim3(N_NODES / 128, H_HEADS), 256, AGG_SMEM>>>(out);
}

// round 13
// speedup vs baseline: 2.2578x; 1.1315x over previous
#include <cuda_runtime.h>
#include <cuda_bf16.h>
#include <cstdint>

#define N_NODES 4096
#define D_IN    256
#define D_OUT   128
#define H_HEADS 4
#define NEG_SLOPE 0.2f
#define NWORDS  (N_NODES / 32)

typedef unsigned long long u64;

// ---------------- scratch (device globals; no allocation allowed) ----------------
__device__ float          g_h[H_HEADS * N_NODES * D_OUT];     // 8 MB fp32 h[head][j][o]
__device__ unsigned       g_mask[N_NODES * NWORDS];            // 2 MB
__device__ float          g_Ei [H_HEADS * N_NODES];
__device__ float          g_Ei2[H_HEADS * N_NODES];
__device__ float2         g_jp [H_HEADS * N_NODES];            // (exp(s_j), exp(0.2*s_j))
__device__ __nv_bfloat16  g_hbhi[H_HEADS * N_NODES * D_OUT];   // 4 MB  h hi [head][j][o]
__device__ __nv_bfloat16  g_hblo[H_HEADS * N_NODES * D_OUT];   // 4 MB  h lo

// ---------------- kernel 1: bit-pack mask = (A>0) | eye ----------------
__global__ void pack_mask_kernel(const int* __restrict__ A) {
    int g    = blockIdx.x * blockDim.x + threadIdx.x;
    int lane = g & 31;
    int word = g >> 5;
    int row  = word >> 7;
    int jw   = word & 127;
    int j    = jw * 32 + lane;
    int v = (A[row * N_NODES + j] > 0) || (j == row);
    unsigned b = __ballot_sync(0xffffffffu, v);
    if (lane == 0) g_mask[word] = b;
}

// ---------------- kernel 2: h = x @ W per head + fused hi/lo bf16 split --------
__global__ __launch_bounds__(256) void h_gemm_kernel(const float* __restrict__ x,
                                                     const float* __restrict__ W) {
    __shared__ __align__(16) float xs[32][129];
    __shared__ __align__(16) float ws[32][128];
    int head    = blockIdx.y;
    int rowbase = blockIdx.x * 128;
    int tid = threadIdx.x;
    int tx  = tid & 15;
    int ty  = tid >> 4;
    int o0  = tx * 8;

    float acc[8][8];
#pragma unroll
    for (int u = 0; u < 8; u++)
#pragma unroll
        for (int i = 0; i < 8; i++) acc[u][i] = 0.f;

    const float* Wh = W + head * D_IN * D_OUT;

    for (int k0 = 0; k0 < D_IN; k0 += 32) {
        __syncthreads();
#pragma unroll
        for (int u = 0; u < 4; u++) {
            int e4  = tid + u * 256;
            int row = e4 >> 3, kq = e4 & 7;
            float4 v = *(const float4*)&x[(rowbase + row) * D_IN + k0 + kq * 4];
            xs[kq * 4 + 0][row] = v.x;
            xs[kq * 4 + 1][row] = v.y;
            xs[kq * 4 + 2][row] = v.z;
            xs[kq * 4 + 3][row] = v.w;
        }
#pragma unroll
        for (int u = 0; u < 4; u++) {
            int e4 = tid + u * 256;
            int kk = e4 >> 5, oq = e4 & 31;
            *(float4*)&ws[kk][oq * 4] = *(const float4*)&Wh[(k0 + kk) * D_OUT + oq * 4];
        }
        __syncthreads();
#pragma unroll
        for (int kk = 0; kk < 32; kk++) {
            float wv[8];
            *(float4*)&wv[0] = *(const float4*)&ws[kk][o0];
            *(float4*)&wv[4] = *(const float4*)&ws[kk][o0 + 4];
#pragma unroll
            for (int u = 0; u < 8; u++) {
                float xv = xs[kk][ty + u * 16];
#pragma unroll
                for (int i = 0; i < 8; i++) acc[u][i] += xv * wv[i];
            }
        }
    }
#pragma unroll
    for (int u = 0; u < 8; u++) {
        int row = rowbase + ty + u * 16;
        size_t idx = (size_t)(head * N_NODES + row) * D_OUT + o0;
        float* dst = &g_h[idx];
        *(float4*)&dst[0] = make_float4(acc[u][0], acc[u][1], acc[u][2], acc[u][3]);
        *(float4*)&dst[4] = make_float4(acc[u][4], acc[u][5], acc[u][6], acc[u][7]);
        // fused hi/lo bf16 split (same [j][o] layout)
        unsigned hp[4], lp[4];
#pragma unroll
        for (int i = 0; i < 4; i++) {
            float v0 = acc[u][2 * i], v1 = acc[u][2 * i + 1];
            __nv_bfloat16 h0 = __float2bfloat16(v0);
            __nv_bfloat16 h1 = __float2bfloat16(v1);
            __nv_bfloat16 l0 = __float2bfloat16(v0 - __bfloat162float(h0));
            __nv_bfloat16 l1 = __float2bfloat16(v1 - __bfloat162float(h1));
            hp[i] = (unsigned)__bfloat16_as_ushort(h0) | ((unsigned)__bfloat16_as_ushort(h1) << 16);
            lp[i] = (unsigned)__bfloat16_as_ushort(l0) | ((unsigned)__bfloat16_as_ushort(l1) << 16);
        }
        *(uint4*)&g_hbhi[idx] = make_uint4(hp[0], hp[1], hp[2], hp[3]);
        *(uint4*)&g_hblo[idx] = make_uint4(lp[0], lp[1], lp[2], lp[3]);
    }
}

// ---------------- kernel 3: s_i, s_j and separable exp factors ----------------
__global__ void sij_kernel(const float* __restrict__ a) {
    int head = blockIdx.y;
    int warp = threadIdx.x >> 5, lane = threadIdx.x & 31;
    int row  = blockIdx.x * 8 + warp;
    const float* hrow = &g_h[(head * N_NODES + row) * D_OUT];
    const float* ah   = a + head * 2 * D_OUT;
    float s1 = 0.f, s2 = 0.f;
#pragma unroll
    for (int u = 0; u < 4; u++) {
        int o = lane + u * 32;
        float hv = hrow[o];
        s1 += hv * ah[o];
        s2 += hv * ah[D_OUT + o];
    }
#pragma unroll
    for (int off = 16; off; off >>= 1) {
        s1 += __shfl_xor_sync(0xffffffffu, s1, off);
        s2 += __shfl_xor_sync(0xffffffffu, s2, off);
    }
    if (lane == 0) {
        g_Ei [head * N_NODES + row] = expf(s1);
        g_Ei2[head * N_NODES + row] = expf(NEG_SLOPE * s1);
        g_jp [head * N_NODES + row] = make_float2(expf(s2), expf(NEG_SLOPE * s2));
    }
}

// ================= mma.sync helpers (sm_80 baseline PTX) =================
#define LDSM_X4(r0, r1, r2, r3, addr) \
    asm volatile("ldmatrix.sync.aligned.m8n8.x4.shared.b16 {%0,%1,%2,%3}, [%4];" \
                 : "=r"(r0), "=r"(r1), "=r"(r2), "=r"(r3) : "r"(addr))
#define LDSM_X4T(r0, r1, r2, r3, addr) \
    asm volatile("ldmatrix.sync.aligned.m8n8.x4.trans.shared.b16 {%0,%1,%2,%3}, [%4];" \
                 : "=r"(r0), "=r"(r1), "=r"(r2), "=r"(r3) : "r"(addr))
#define MMA_BF16(d, a0, a1, a2, a3, b0, b1) \
    asm volatile("mma.sync.aligned.m16n8k16.row.col.f32.bf16.bf16.f32 " \
                 "{%0,%1,%2,%3}, {%4,%5,%6,%7}, {%8,%9}, {%0,%1,%2,%3};" \
                 : "+f"((d)[0]), "+f"((d)[1]), "+f"((d)[2]), "+f"((d)[3]) \
                 : "r"(a0), "r"(a1), "r"(a2), "r"(a3), "r"(b0), "r"(b1))

__device__ __forceinline__ uint32_t smem_u32(const void* p) {
    uint32_t a;
    asm("{ .reg .u64 t; cvta.to.shared.u64 t, %1; cvt.u32.u64 %0, t; }" : "=r"(a) : "l"(p));
    return a;
}

// dynamic smem: 2 stages x (WHI 16K | WLO 16K | HHI 16K | HLO 16K) + Z 1K
#define SM_WHI  0
#define SM_WLO  16384
#define SM_HHI  32768
#define SM_HLO  49152
#define STG_SZ  65536
#define SM_Z    131072
#define AGG_SMEM 132096

// ---------------- kernel 4: double-buffered mma.sync aggregation ----------------
// Grid (32, 4), 256 threads (8 warps). Per iteration: LDG H(t+1) -> regs,
// MMA(t) on buf[cur], W-gen(t+1) + STS H(t+1) into buf[nxt], ONE sync.
__global__ __launch_bounds__(256) void agg_kernel(float* __restrict__ out) {
    extern __shared__ __align__(1024) char dsm[];
    uint32_t sb = smem_u32(dsm);
    int tid  = threadIdx.x;
    int lane = tid & 31;
    int wid  = tid >> 5;
    int head = blockIdx.y;
    int rowbase = blockIdx.x * 128;

    int wy = wid >> 1, wx = wid & 1;

    // weight-gen mapping: 2 threads per row (seg = j-half of 64-tile)
    int grow = tid & 127, seg = tid >> 7;
    float eiw  = g_Ei [head * N_NODES + rowbase + grow];
    float ei2w = g_Ei2[head * N_NODES + rowbase + grow];
    float Zrow = 0.f;
    const float2* jpb = &g_jp[head * N_NODES];
    const unsigned* maskrow = &g_mask[(size_t)(rowbase + grow) * NWORDS];
    int wgenbase = grow * 128;
    int wrx = grow & 7;

    // H staging mapping
    int hj  = (tid >> 4);        // j row base for r-chunks: j = hj + r*16
    int hoc = tid & 15;
    const uint4* hhiG = (const uint4*)(g_hbhi + (size_t)head * N_NODES * D_OUT);
    const uint4* hloG = (const uint4*)(g_hblo + (size_t)head * N_NODES * D_OUT);

    float acc[2][8][4];
#pragma unroll
    for (int m = 0; m < 2; m++)
#pragma unroll
        for (int n = 0; n < 8; n++)
#pragma unroll
            for (int e = 0; e < 4; e++) acc[m][n][e] = 0.f;

    int lt = lane >> 3, lr = lane & 7;

    // ---- helpers ----
    auto gen_w = [&](int t, int s) {
        int jt = t * 64;
        unsigned mword = maskrow[(jt >> 5) + seg];
        char* wb = dsm + s * STG_SZ;
#pragma unroll
        for (int cc = 0; cc < 4; cc++) {
            int kc = seg * 4 + cc;
            unsigned hiP[4], loP[4];
#pragma unroll
            for (int e2 = 0; e2 < 4; e2++) {
                int bit = cc * 8 + e2 * 2;
                int jg  = jt + seg * 32 + cc * 8 + e2 * 2;
                float2 pa = jpb[jg];
                float2 pb = jpb[jg + 1];
                float va = fmaxf(eiw * pa.x, ei2w * pa.y);
                float vb = fmaxf(eiw * pb.x, ei2w * pb.y);
                float wa = ((mword >> bit) & 1u) ? va : 0.f;
                float wb2 = ((mword >> (bit + 1)) & 1u) ? vb : 0.f;
                Zrow += wa + wb2;
                __nv_bfloat16 ha = __float2bfloat16(wa);
                __nv_bfloat16 hb = __float2bfloat16(wb2);
                __nv_bfloat16 la = __float2bfloat16(wa - __bfloat162float(ha));
                __nv_bfloat16 lb = __float2bfloat16(wb2 - __bfloat162float(hb));
                hiP[e2] = (unsigned)__bfloat16_as_ushort(ha) | ((unsigned)__bfloat16_as_ushort(hb) << 16);
                loP[e2] = (unsigned)__bfloat16_as_ushort(la) | ((unsigned)__bfloat16_as_ushort(lb) << 16);
            }
            int sw = wgenbase + ((kc ^ wrx) << 4);
            *(uint4*)(wb + SM_WHI + sw) = make_uint4(hiP[0], hiP[1], hiP[2], hiP[3]);
            *(uint4*)(wb + SM_WLO + sw) = make_uint4(loP[0], loP[1], loP[2], loP[3]);
        }
    };
    auto ldg_h = [&](int t, uint4* hh, uint4* hl) {
        int jt = t * 64;
#pragma unroll
        for (int r = 0; r < 4; r++) {
            size_t gidx = (size_t)(jt + hj + r * 16) * 16 + hoc;
            hh[r] = hhiG[gidx];
            hl[r] = hloG[gidx];
        }
    };
    auto sts_h = [&](int s, const uint4* hh, const uint4* hl) {
        char* hb = dsm + s * STG_SZ;
#pragma unroll
        for (int r = 0; r < 4; r++) {
            int j = hj + r * 16;
            int ad = j * 256 + ((hoc ^ (j & 7)) << 4);
            *(uint4*)(hb + SM_HHI + ad) = hh[r];
            *(uint4*)(hb + SM_HLO + ad) = hl[r];
        }
    };

    // ---- prologue: fill stage 0 ----
    {
        uint4 hh[4], hl[4];
        ldg_h(0, hh, hl);
        gen_w(0, 0);
        sts_h(0, hh, hl);
    }
    __syncthreads();

    for (int t = 0; t < 64; t++) {
        int cur = t & 1, nxt = cur ^ 1;
        uint4 hh[4], hl[4];
        if (t + 1 < 64) ldg_h(t + 1, hh, hl);     // in flight during MMA

        uint32_t bufb = sb + cur * STG_SZ;
        // ---- MMA on buf[cur] ----
#pragma unroll
        for (int ks = 0; ks < 4; ks++) {
            uint32_t ahi[2][4], alo[2][4];
#pragma unroll
            for (int mm = 0; mm < 2; mm++) {
                int row = wy * 32 + mm * 16 + (lt & 1) * 8 + lr;
                int kc  = ks * 2 + (lt >> 1);
                uint32_t aaddr = bufb + SM_WHI + row * 128 + ((kc ^ (row & 7)) << 4);
                LDSM_X4(ahi[mm][0], ahi[mm][1], ahi[mm][2], ahi[mm][3], aaddr);
                LDSM_X4(alo[mm][0], alo[mm][1], alo[mm][2], alo[mm][3], aaddr + 16384);
            }
#pragma unroll
            for (int nn = 0; nn < 4; nn++) {
                int j  = ks * 16 + (lt & 1) * 8 + lr;
                int oc = wx * 8 + nn * 2 + (lt >> 1);
                uint32_t baddr = bufb + SM_HHI + j * 256 + ((oc ^ (j & 7)) << 4);
                uint32_t bh0, bh1, bh2, bh3, bl0, bl1, bl2, bl3;
                LDSM_X4T(bh0, bh1, bh2, bh3, baddr);
                LDSM_X4T(bl0, bl1, bl2, bl3, baddr + 16384);
#pragma unroll
                for (int mm = 0; mm < 2; mm++) {
                    MMA_BF16(acc[mm][nn * 2],     ahi[mm][0], ahi[mm][1], ahi[mm][2], ahi[mm][3], bh0, bh1);
                    MMA_BF16(acc[mm][nn * 2 + 1], ahi[mm][0], ahi[mm][1], ahi[mm][2], ahi[mm][3], bh2, bh3);
                    MMA_BF16(acc[mm][nn * 2],     ahi[mm][0], ahi[mm][1], ahi[mm][2], ahi[mm][3], bl0, bl1);
                    MMA_BF16(acc[mm][nn * 2 + 1], ahi[mm][0], ahi[mm][1], ahi[mm][2], ahi[mm][3], bl2, bl3);
                    MMA_BF16(acc[mm][nn * 2],     alo[mm][0], alo[mm][1], alo[mm][2], alo[mm][3], bh0, bh1);
                    MMA_BF16(acc[mm][nn * 2 + 1], alo[mm][0], alo[mm][1], alo[mm][2], alo[mm][3], bh2, bh3);
                }
            }
        }
        // ---- stage t+1 into buf[nxt] ----
        if (t + 1 < 64) {
            gen_w(t + 1, nxt);
            sts_h(nxt, hh, hl);
        }
        __syncthreads();
    }

    // ---- Z + epilogue ----
    ((float*)(dsm + SM_Z))[tid] = Zrow;
    __syncthreads();
    const float* zs = (const float*)(dsm + SM_Z);

#pragma unroll
    for (int mm = 0; mm < 2; mm++) {
        int r0 = wy * 32 + mm * 16 + (lane >> 2);
        int r1 = r0 + 8;
        float iz0 = 1.f / (zs[r0] + zs[128 + r0]);
        float iz1 = 1.f / (zs[r1] + zs[128 + r1]);
        float* d0 = out + (size_t)(rowbase + r0) * (H_HEADS * D_OUT) + head * D_OUT;
        float* d1 = out + (size_t)(rowbase + r1) * (H_HEADS * D_OUT) + head * D_OUT;
#pragma unroll
        for (int nn = 0; nn < 8; nn++) {
            int col = wx * 64 + nn * 8 + (lane & 3) * 2;
            *(float2*)(d0 + col) = make_float2(acc[mm][nn][0] * iz0, acc[mm][nn][1] * iz0);
            *(float2*)(d1 + col) = make_float2(acc[mm][nn][2] * iz1, acc[mm][nn][3] * iz1);
        }
    }
}

// ---------------- launch ----------------
extern "C" void kernel_launch(void* const* d_in, const int* in_sizes, int n_in,
                              void* d_out, int out_size) {
    const float* x = (const float*)d_in[0];
    const int*   A = (const int*)  d_in[1];
    const float* W = (const float*)d_in[2];
    const float* a = (const float*)d_in[3];
    float* out = (float*)d_out;

    cudaFuncSetAttribute(agg_kernel, cudaFuncAttributeMaxDynamicSharedMemorySize, AGG_SMEM);

    pack_mask_kernel<<<(N_NODES * N_NODES) / 256, 256>>>(A);
    h_gemm_kernel<<<dim3(N_NODES / 128, H_HEADS), 256>>>(x, W);
    sij_kernel<<<dim3(N_NODES / 8, H_HEADS), 256>>>(a);
    agg_kernel<<<dim3(N_NODES / 128, H_HEADS), 256, AGG_SMEM>>>(out);
}